// round 6
// baseline (speedup 1.0000x reference)
#include <cuda_runtime.h>
#include <cuda_bf16.h>

#define B_    16
#define A_    262144
#define G_    128
#define NTHR  256
#define NBLK  (A_ / NTHR)      /* 1024 */
#define NWARP (NTHR / 32)      /* 8 */

// Per-(batch, block) partials: {sum, count}. Written fresh every launch.
__device__ float2   g_part[B_ * NBLK];
__device__ unsigned g_done = 0;   // reset by the last block each launch

__global__ void __launch_bounds__(NTHR)
retina_loss_fused(const float4* __restrict__ bbox,     // [B, A, 4]
                  const float4* __restrict__ anchors,  // [A, 4]
                  const float4* __restrict__ gt,       // [B, G, 4]
                  const int*    __restrict__ midx,     // [B, A]
                  float*        __restrict__ out)
{
    __shared__ float s_sum[B_ * NWARP];
    __shared__ int   s_cnt[B_ * NWARP];
    __shared__ float s_img[B_];
    __shared__ unsigned s_ticket;

    const int tid  = threadIdx.x;
    const int lane = tid & 31;
    const int warp = tid >> 5;
    const int a    = blockIdx.x * NTHR + tid;   // NBLK*NTHR == A_, no guard

    // Anchor loaded ONCE, reused for all 16 batches.
    float4 an = anchors[a];
    float ex_w  = an.z - an.x;
    float ex_h  = an.w - an.y;
    float ex_cx = an.x + 0.5f * ex_w;
    float ex_cy = an.y + 0.5f * ex_h;
    float iw = 1.0f / ex_w;
    float ih = 1.0f / ex_h;

    // Two halves of 8 batches each: keeps register peak modest while the
    // 8 iterations inside each half are fully independent (high LDG MLP).
#pragma unroll
    for (int half = 0; half < 2; half++) {
        int m[8];
#pragma unroll
        for (int j = 0; j < 8; j++)
            m[j] = midx[(size_t)(half * 8 + j) * A_ + a];

        float v[8];
#pragma unroll
        for (int j = 0; j < 8; j++) {
            const int  b  = half * 8 + j;
            const bool fg = (m[j] >= 0);
            float4 r = bbox[(size_t)b * A_ + a];
            float4 g = gt[b * G_ + (fg ? m[j] : 0)];   // 32 KB, L1-resident

            float gw  = g.z - g.x;
            float gh  = g.w - g.y;
            float gcx = g.x + 0.5f * gw;
            float gcy = g.y + 0.5f * gh;

            float dx = (gcx - ex_cx) * iw;
            float dy = (gcy - ex_cy) * ih;
            float dw = __logf(gw * iw);   // MUFU; abs err ~1e-6 << 1e-3
            float dh = __logf(gh * ih);

            float l1 = fabsf(r.x - dx) + fabsf(r.y - dy)
                     + fabsf(r.z - dw) + fabsf(r.w - dh);
            v[j] = fg ? l1 : 0.0f;

            // Count: ballot (1 instr) + lane-0 popc/STS (no result latency).
            unsigned blt = __ballot_sync(0xffffffffu, fg);
            if (lane == 0) s_cnt[b * NWARP + warp] = __popc(blt);
        }

        // Transpose-reduce: sum 8 values over 32 lanes in 9 SHFLs (vs 40
        // for per-batch shfl_down chains). After the halving stages, lanes
        // 4j..4j+3 all hold batch j's warp total (j = lane>>2). Order is
        // fixed -> bit-deterministic.
#pragma unroll
        for (int i = 0; i < 4; i++) {          // mask 16: 8 -> 4 values
            float send = (lane & 16) ? v[i] : v[i + 4];
            float recv = __shfl_xor_sync(0xffffffffu, send, 16);
            float keep = (lane & 16) ? v[i + 4] : v[i];
            v[i] = keep + recv;
        }
#pragma unroll
        for (int i = 0; i < 2; i++) {          // mask 8: 4 -> 2 values
            float send = (lane & 8) ? v[i] : v[i + 2];
            float recv = __shfl_xor_sync(0xffffffffu, send, 8);
            float keep = (lane & 8) ? v[i + 2] : v[i];
            v[i] = keep + recv;
        }
        {                                      // mask 4: 2 -> 1 value
            float send = (lane & 4) ? v[0] : v[1];
            float recv = __shfl_xor_sync(0xffffffffu, send, 4);
            float keep = (lane & 4) ? v[1] : v[0];
            v[0] = keep + recv;
        }
        v[0] += __shfl_xor_sync(0xffffffffu, v[0], 2);   // mask 2
        v[0] += __shfl_xor_sync(0xffffffffu, v[0], 1);   // mask 1

        if ((lane & 3) == 0)
            s_sum[(half * 8 + (lane >> 2)) * NWARP + warp] = v[0];
    }
    __syncthreads();

    // Deterministic block combine: thread t (<16) owns batch t.
    if (tid < B_) {
        float s = 0.0f;
        int   c = 0;
#pragma unroll
        for (int w = 0; w < NWARP; w++) {
            s += s_sum[tid * NWARP + w];
            c += s_cnt[tid * NWARP + w];
        }
        g_part[tid * NBLK + blockIdx.x] = make_float2(s, (float)c);
    }

    // ---- last-block-done final reduction ----
    __threadfence();
    __syncthreads();
    if (tid == 0)
        s_ticket = atomicAdd(&g_done, 1u);
    __syncthreads();

    if (s_ticket == (unsigned)(NBLK - 1)) {
        // All partials are L2-visible. Warp-per-batch, fixed order.
        for (int b = warp; b < B_; b += NWARP) {
            float s = 0.0f;
            float c = 0.0f;
#pragma unroll 8
            for (int i = lane; i < NBLK; i += 32) {
                float2 p = __ldcg(&g_part[b * NBLK + i]);
                s += p.x;
                c += p.y;
            }
#pragma unroll
            for (int o = 16; o > 0; o >>= 1) {
                s += __shfl_down_sync(0xffffffffu, s, o);
                c += __shfl_down_sync(0xffffffffu, c, o);
            }
            if (lane == 0)
                s_img[b] = s / fmaxf(c, 1.0f);
        }
        __syncthreads();
        if (tid == 0) {
            float tot = 0.0f;
#pragma unroll
            for (int b = 0; b < B_; b++) tot += s_img[b];
            *out = tot * (1.0f / (float)B_);
            g_done = 0;           // reset for the next graph replay
        }
    }
}

extern "C" void kernel_launch(void* const* d_in, const int* in_sizes, int n_in,
                              void* d_out, int out_size)
{
    const float4* bbox    = (const float4*)d_in[0];  // bbox_regression [B, A, 4] f32
    const float4* anchors = (const float4*)d_in[1];  // anchors [A, 4] f32
    const float4* gt      = (const float4*)d_in[2];  // gt_boxes [B, G, 4] f32
    const int*    midx    = (const int*)d_in[3];     // matched_idxs [B, A] i32

    retina_loss_fused<<<NBLK, NTHR>>>(bbox, anchors, gt, midx, (float*)d_out);
}